// round 5
// baseline (speedup 1.0000x reference)
#include <cuda_runtime.h>
#include <cstdint>
#include <cstddef>

// ---------------- problem constants ----------------
#define MTOT 4096
#define NTOT 2048
#define K1   1024
#define K2   2048

#define BM 128
#define BN 128
#define BK 32
#define NS 3

#define KT1  (K1 / BK)           // 32
#define KTOT ((K1 + K2) / BK)    // 96

#define STAGE_A  (BM * BK * 4)               // 16384 B
#define STAGE_SZ (2 * STAGE_A)               // 32768 B (A then B)
#define SMEM_BYTES (NS * STAGE_SZ)           // 98304 B

// ---------------- scratch (__device__ globals: allocation-free) ----------------
__device__ float g_rh[MTOT * (size_t)NTOT];
__device__ float g_zb[MTOT * (size_t)NTOT];

// ---------------- helpers ----------------
__device__ __forceinline__ uint32_t smem_u32(const void* p) {
    uint32_t a;
    asm("{ .reg .u64 t; cvta.to.shared.u64 t, %1; cvt.u32.u64 %0, t; }" : "=r"(a) : "l"(p));
    return a;
}

__device__ __forceinline__ void cp16(uint32_t dst, const void* src) {
    asm volatile("cp.async.cg.shared.global [%0], [%1], 16;" :: "r"(dst), "l"(src));
}
__device__ __forceinline__ void cp_commit() {
    asm volatile("cp.async.commit_group;" ::: "memory");
}
__device__ __forceinline__ void cp_wait() {
    asm volatile("cp.async.wait_group %0;" :: "n"(NS - 1) : "memory");
}

// XOR-swizzled smem address for element (r, k) of a [rows][32] fp32 tile.
// 16B chunk c of row r lands at chunk (c ^ (r & 7)); row stride 128 B.
__device__ __forceinline__ uint32_t frag_addr(uint32_t base, int r, int k) {
    return base + (uint32_t)r * 128u
         + (uint32_t)(((((k >> 2) ^ (r & 7)) << 4)) | ((k & 3) << 2));
}

// LDS + round-to-nearest tf32 (removes the biased truncation the MMA would do)
__device__ __forceinline__ uint32_t lds_tf32(uint32_t addr) {
    float v;
    asm volatile("ld.shared.f32 %0, [%1];" : "=f"(v) : "r"(addr));
    uint32_t r;
    asm("cvt.rna.tf32.f32 %0, %1;" : "=r"(r) : "f"(v));
    return r;
}

__device__ __forceinline__ void mma_tf32(float* c, const uint32_t* a, const uint32_t* b) {
    asm volatile(
        "mma.sync.aligned.m16n8k8.row.col.f32.tf32.tf32.f32 "
        "{%0,%1,%2,%3}, {%4,%5,%6,%7}, {%8,%9}, {%0,%1,%2,%3};"
        : "+f"(c[0]), "+f"(c[1]), "+f"(c[2]), "+f"(c[3])
        : "r"(a[0]), "r"(a[1]), "r"(a[2]), "r"(a[3]), "r"(b[0]), "r"(b[1]));
}

__device__ __forceinline__ float sigf(float v) { return 1.f / (1.f + __expf(-v)); }
__device__ __forceinline__ float tanhfast(float v) { return 2.f / (1.f + __expf(-2.f * v)) - 1.f; }

// ---------------- tile loader (dual K-source) ----------------
__device__ __forceinline__ void load_tile(int kt, uint32_t st, int tid, int tm, int tn,
                                          const float* __restrict__ A1, const float* __restrict__ B1,
                                          const float* __restrict__ A2, const float* __restrict__ B2) {
    const float* As; const float* Bs; int ld, ko;
    if (kt < KT1) { As = A1; Bs = B1; ld = K1; ko = kt * BK; }
    else          { As = A2; Bs = B2; ld = K2; ko = (kt - KT1) * BK; }

    const float* abase = As + (size_t)tm * BM * ld + ko;
    const float* bbase = Bs + (size_t)tn * BN * ld + ko;
#pragma unroll
    for (int i = 0; i < 4; i++) {
        const int idx = i * 256 + tid;
        const int r = idx >> 3;           // 0..127
        const int c = idx & 7;            // 16B chunk in row
        const uint32_t soff = (uint32_t)r * 128u + (uint32_t)((c ^ (r & 7)) << 4);
        cp16(st + soff,            abase + (size_t)r * ld + c * 4);
        cp16(st + STAGE_A + soff,  bbase + (size_t)r * ld + c * 4);
    }
}

// ---------------- fused dual-source GEMM ----------------
// acc[M,N] = A1@B1^T (K=1024) + A2@B2^T (K=2048), epilogue by EPI:
//  EPI 0 (r): out = sigmoid(acc+bias) * hprev          -> g_rh
//  EPI 1 (z): out = sigmoid(acc+bias)                  -> g_zb
//  EPI 2 (h): out = z*tanh(acc+bias) + (1-z)*hprev     -> d_out
template <int EPI>
__global__ void __launch_bounds__(256, 2) gru_gemm(
    const float* __restrict__ A1, const float* __restrict__ B1,
    const float* __restrict__ A2, const float* __restrict__ B2,
    const float* __restrict__ bias, const float* __restrict__ hprev,
    const float* __restrict__ zbuf, float* __restrict__ out)
{
    extern __shared__ char smem[];
    const uint32_t sbase = smem_u32(smem);
    const int tid = threadIdx.x;
    const int wid = tid >> 5;
    const int lid = tid & 31;
    const int g   = lid >> 2;     // group id 0..7
    const int tq  = lid & 3;      // thread-in-group
    const int wm  = wid >> 1;     // 0..3 (M)
    const int wn  = wid & 1;      // 0..1 (N)
    const int tm  = blockIdx.x & 31;   // 32 M tiles
    const int tn  = blockIdx.x >> 5;   // 16 N tiles

    float acc[2][8][4];
#pragma unroll
    for (int mt = 0; mt < 2; mt++)
#pragma unroll
        for (int nt = 0; nt < 8; nt++)
#pragma unroll
            for (int i = 0; i < 4; i++) acc[mt][nt][i] = 0.f;

    // prefetch stages 0..NS-2
#pragma unroll
    for (int p = 0; p < NS - 1; p++) {
        load_tile(p, sbase + p * STAGE_SZ, tid, tm, tn, A1, B1, A2, B2);
        cp_commit();
    }

#pragma unroll 1
    for (int kt = 0; kt < KTOT; kt++) {
        const int lt = kt + NS - 1;
        if (lt < KTOT)
            load_tile(lt, sbase + (lt % NS) * STAGE_SZ, tid, tm, tn, A1, B1, A2, B2);
        cp_commit();
        cp_wait();            // stage kt%NS complete
        __syncthreads();

        const uint32_t sA = sbase + (kt % NS) * STAGE_SZ;
        const uint32_t sB = sA + STAGE_A;

#pragma unroll
        for (int q = 0; q < 4; q++) {
            const int k0 = q * 8;
            uint32_t a[2][4];
#pragma unroll
            for (int mt = 0; mt < 2; mt++) {
                const int r = wm * 32 + mt * 16 + g;
                a[mt][0] = lds_tf32(frag_addr(sA, r,     k0 + tq));
                a[mt][1] = lds_tf32(frag_addr(sA, r + 8, k0 + tq));
                a[mt][2] = lds_tf32(frag_addr(sA, r,     k0 + tq + 4));
                a[mt][3] = lds_tf32(frag_addr(sA, r + 8, k0 + tq + 4));
            }
            uint32_t b[8][2];
#pragma unroll
            for (int nt = 0; nt < 8; nt++) {
                const int n = wn * 64 + nt * 8 + g;
                b[nt][0] = lds_tf32(frag_addr(sB, n, k0 + tq));
                b[nt][1] = lds_tf32(frag_addr(sB, n, k0 + tq + 4));
            }
#pragma unroll
            for (int mt = 0; mt < 2; mt++)
#pragma unroll
                for (int nt = 0; nt < 8; nt++)
                    mma_tf32(acc[mt][nt], a[mt], b[nt]);
        }
        __syncthreads();      // protect stage about to be overwritten next iter
    }

    // ---------------- epilogue ----------------
#pragma unroll
    for (int mt = 0; mt < 2; mt++) {
#pragma unroll
        for (int nt = 0; nt < 8; nt++) {
            const int n = tn * BN + wn * 64 + nt * 8 + tq * 2;
            const float2 bi = *(const float2*)(bias + n);
#pragma unroll
            for (int half = 0; half < 2; half++) {
                const int m = tm * BM + wm * 32 + mt * 16 + g + half * 8;
                const size_t idx = (size_t)m * NTOT + n;
                float v0 = acc[mt][nt][half * 2 + 0] + bi.x;
                float v1 = acc[mt][nt][half * 2 + 1] + bi.y;
                float2 o;
                if (EPI == 0) {
                    const float2 h = *(const float2*)(hprev + idx);
                    o.x = sigf(v0) * h.x;
                    o.y = sigf(v1) * h.y;
                } else if (EPI == 1) {
                    o.x = sigf(v0);
                    o.y = sigf(v1);
                } else {
                    const float2 h = *(const float2*)(hprev + idx);
                    const float2 z = *(const float2*)(zbuf + idx);
                    o.x = z.x * tanhfast(v0) + (1.f - z.x) * h.x;
                    o.y = z.y * tanhfast(v1) + (1.f - z.y) * h.y;
                }
                *(float2*)(out + idx) = o;
            }
        }
    }
}

// ---------------- host launcher ----------------
extern "C" void kernel_launch(void* const* d_in, const int* in_sizes, int n_in,
                              void* d_out, int out_size) {
    (void)in_sizes; (void)n_in; (void)out_size;
    // metadata order: x, hprev, Wh, Wz, Wr, Uh, Uz, Ur, bh, bz, br
    const float* x     = (const float*)d_in[0];
    const float* hprev = (const float*)d_in[1];
    const float* Wh    = (const float*)d_in[2];
    const float* Wz    = (const float*)d_in[3];
    const float* Wr    = (const float*)d_in[4];
    const float* Uh    = (const float*)d_in[5];
    const float* Uz    = (const float*)d_in[6];
    const float* Ur    = (const float*)d_in[7];
    const float* bh    = (const float*)d_in[8];
    const float* bz    = (const float*)d_in[9];
    const float* br    = (const float*)d_in[10];
    float* out = (float*)d_out;

    float *prh, *pzb;
    cudaGetSymbolAddress((void**)&prh, g_rh);
    cudaGetSymbolAddress((void**)&pzb, g_zb);

    cudaFuncSetAttribute(gru_gemm<0>, cudaFuncAttributeMaxDynamicSharedMemorySize, SMEM_BYTES);
    cudaFuncSetAttribute(gru_gemm<1>, cudaFuncAttributeMaxDynamicSharedMemorySize, SMEM_BYTES);
    cudaFuncSetAttribute(gru_gemm<2>, cudaFuncAttributeMaxDynamicSharedMemorySize, SMEM_BYTES);

    const dim3 grid(512), block(256);
    // r-gate: g_rh = sigmoid(x@Wr^T + h@Ur^T + br) * hprev
    gru_gemm<0><<<grid, block, SMEM_BYTES>>>(x, Wr, hprev, Ur, br, hprev, nullptr, prh);
    // z-gate: g_zb = sigmoid(x@Wz^T + h@Uz^T + bz)
    gru_gemm<1><<<grid, block, SMEM_BYTES>>>(x, Wz, hprev, Uz, bz, nullptr, nullptr, pzb);
    // h-gate: out = z * tanh(x@Wh^T + rh@Uh^T + bh) + (1-z) * hprev
    gru_gemm<2><<<grid, block, SMEM_BYTES>>>(x, Wh, prh, Uh, bh, hprev, pzb, out);
}

// round 6
// speedup vs baseline: 1.0536x; 1.0536x over previous
#include <cuda_runtime.h>
#include <cstdint>
#include <cstddef>

// ---------------- problem constants ----------------
#define MTOT 4096
#define NTOT 2048
#define K1   1024
#define K2   2048

#define BM 128
#define BN 128
#define BK 32
#define NS 3

#define KT1  (K1 / BK)           // 32
#define KTOT ((K1 + K2) / BK)    // 96

#define STAGE_A  (BM * BK * 4)               // 16384 B
#define STAGE_SZ (2 * STAGE_A)               // 32768 B (A then B)
#define SMEM_BYTES (NS * STAGE_SZ)           // 98304 B

// ---------------- scratch (__device__ globals: allocation-free) ----------------
__device__ float g_x [MTOT * (size_t)K1];
__device__ float g_h [MTOT * (size_t)K2];
__device__ float g_Wr[NTOT * (size_t)K1];
__device__ float g_Wz[NTOT * (size_t)K1];
__device__ float g_Wh[NTOT * (size_t)K1];
__device__ float g_Ur[NTOT * (size_t)K2];
__device__ float g_Uz[NTOT * (size_t)K2];
__device__ float g_Uh[NTOT * (size_t)K2];
__device__ float g_rh[MTOT * (size_t)NTOT];
__device__ float g_zb[MTOT * (size_t)NTOT];

// ---------------- helpers ----------------
__device__ __forceinline__ uint32_t smem_u32(const void* p) {
    uint32_t a;
    asm("{ .reg .u64 t; cvta.to.shared.u64 t, %1; cvt.u32.u64 %0, t; }" : "=r"(a) : "l"(p));
    return a;
}

__device__ __forceinline__ void cp16(uint32_t dst, const void* src) {
    asm volatile("cp.async.cg.shared.global [%0], [%1], 16;" :: "r"(dst), "l"(src));
}
__device__ __forceinline__ void cp_commit() {
    asm volatile("cp.async.commit_group;" ::: "memory");
}
__device__ __forceinline__ void cp_wait() {
    asm volatile("cp.async.wait_group %0;" :: "n"(NS - 1) : "memory");
}

// ldmatrix x4 (b16): four 8x8 b16 matrices == four 8row x 4col fp32 tiles.
// Fragment map (thread t -> row t/4, col t%4) matches mma.tf32 A/B layouts.
__device__ __forceinline__ void ldm4(uint32_t* r, uint32_t addr) {
    asm volatile("ldmatrix.sync.aligned.m8n8.x4.shared.b16 {%0,%1,%2,%3}, [%4];"
                 : "=r"(r[0]), "=r"(r[1]), "=r"(r[2]), "=r"(r[3]) : "r"(addr));
}

__device__ __forceinline__ void mma_tf32(float* c, const uint32_t* a, uint32_t b0, uint32_t b1) {
    asm volatile(
        "mma.sync.aligned.m16n8k8.row.col.f32.tf32.tf32.f32 "
        "{%0,%1,%2,%3}, {%4,%5,%6,%7}, {%8,%9}, {%0,%1,%2,%3};"
        : "+f"(c[0]), "+f"(c[1]), "+f"(c[2]), "+f"(c[3])
        : "r"(a[0]), "r"(a[1]), "r"(a[2]), "r"(a[3]), "r"(b0), "r"(b1));
}

__device__ __forceinline__ float tf32r(float x) {
    float r;
    asm("cvt.rna.tf32.f32 %0, %1;" : "=f"(r) : "f"(x));
    return r;
}
__device__ __forceinline__ float sigf(float v) { return 1.f / (1.f + __expf(-v)); }
__device__ __forceinline__ float tanhfast(float v) { return 2.f / (1.f + __expf(-2.f * v)) - 1.f; }

// ---------------- tf32 rounding pre-pass (one launch, 8 segments) ----------------
struct RoundSegs {
    const float4* src[8];
    float4*       dst[8];
    int           n4[8];
};

__global__ void round_all(RoundSegs S) {
    const int s = blockIdx.y;
    const float4* __restrict__ in = S.src[s];
    float4* __restrict__ out = S.dst[s];
    const int n4 = S.n4[s];
    for (int i = blockIdx.x * blockDim.x + threadIdx.x; i < n4; i += gridDim.x * blockDim.x) {
        float4 v = in[i];
        v.x = tf32r(v.x); v.y = tf32r(v.y); v.z = tf32r(v.z); v.w = tf32r(v.w);
        out[i] = v;
    }
}

// ---------------- tile loader (dual K-source) ----------------
__device__ __forceinline__ void load_tile(int kt, uint32_t st, int tid, int tm, int tn,
                                          const float* __restrict__ A1, const float* __restrict__ B1,
                                          const float* __restrict__ A2, const float* __restrict__ B2) {
    const float* As; const float* Bs; int ld, ko;
    if (kt < KT1) { As = A1; Bs = B1; ld = K1; ko = kt * BK; }
    else          { As = A2; Bs = B2; ld = K2; ko = (kt - KT1) * BK; }

    const float* abase = As + (size_t)tm * BM * ld + ko;
    const float* bbase = Bs + (size_t)tn * BN * ld + ko;
#pragma unroll
    for (int i = 0; i < 4; i++) {
        const int idx = i * 256 + tid;
        const int r = idx >> 3;           // 0..127
        const int c = idx & 7;            // 16B chunk in row
        const uint32_t soff = (uint32_t)r * 128u + (uint32_t)((c ^ (r & 7)) << 4);
        cp16(st + soff,            abase + (size_t)r * ld + c * 4);
        cp16(st + STAGE_A + soff,  bbase + (size_t)r * ld + c * 4);
    }
}

// ---------------- fused dual-source GEMM ----------------
// acc[M,N] = A1@B1^T (K=1024) + A2@B2^T (K=2048), epilogue by EPI:
//  EPI 0 (r): out = tf32(sigmoid(acc+bias) * hprev)    -> g_rh
//  EPI 1 (z): out = sigmoid(acc+bias)                  -> g_zb
//  EPI 2 (h): out = z*tanh(acc+bias) + (1-z)*hprev     -> d_out
template <int EPI>
__global__ void __launch_bounds__(256, 2) gru_gemm(
    const float* __restrict__ A1, const float* __restrict__ B1,
    const float* __restrict__ A2, const float* __restrict__ B2,
    const float* __restrict__ bias, const float* __restrict__ hprev,
    const float* __restrict__ zbuf, float* __restrict__ out)
{
    extern __shared__ char smem[];
    const uint32_t sbase = smem_u32(smem);
    const int tid = threadIdx.x;
    const int wid = tid >> 5;
    const int lid = tid & 31;
    const int g   = lid >> 2;     // group id 0..7
    const int tq  = lid & 3;      // thread-in-group
    const int wm  = wid >> 1;     // 0..3 (M)
    const int wn  = wid & 1;      // 0..1 (N)
    const int tm  = blockIdx.x & 31;   // 32 M tiles (fast dim -> same-tn blocks adjacent)
    const int tn  = blockIdx.x >> 5;   // 16 N tiles

    // ldmatrix per-thread row addressing: lane -> (matrix mi = lid/8, row-in-matrix lid%8)
    const int lr = lid & 7;
    const int mi = lid >> 3;
    const int lo = mi & 1;        // +8 rows
    const int hi = mi >> 1;       // +4 k (chunk)

    uint32_t aoff[2]; int ars[2];
#pragma unroll
    for (int mt = 0; mt < 2; mt++) {
        const int r = wm * 32 + mt * 16 + lo * 8 + lr;
        aoff[mt] = (uint32_t)r * 128u;
        ars[mt] = r & 7;
    }
    uint32_t boff[4]; int brs[4];
#pragma unroll
    for (int j = 0; j < 4; j++) {
        const int r = wn * 64 + j * 16 + lo * 8 + lr;
        boff[j] = (uint32_t)r * 128u;
        brs[j] = r & 7;
    }

    float acc[2][8][4];
#pragma unroll
    for (int mt = 0; mt < 2; mt++)
#pragma unroll
        for (int nt = 0; nt < 8; nt++)
#pragma unroll
            for (int i = 0; i < 4; i++) acc[mt][nt][i] = 0.f;

    // prefetch stages 0..NS-2
#pragma unroll
    for (int p = 0; p < NS - 1; p++) {
        load_tile(p, sbase + p * STAGE_SZ, tid, tm, tn, A1, B1, A2, B2);
        cp_commit();
    }

#pragma unroll 1
    for (int kt = 0; kt < KTOT; kt++) {
        const int lt = kt + NS - 1;
        if (lt < KTOT)
            load_tile(lt, sbase + (lt % NS) * STAGE_SZ, tid, tm, tn, A1, B1, A2, B2);
        cp_commit();
        cp_wait();            // stage kt%NS complete
        __syncthreads();

        const uint32_t sA = sbase + (kt % NS) * STAGE_SZ;
        const uint32_t sB = sA + STAGE_A;

#pragma unroll
        for (int q = 0; q < 4; q++) {
            const int ch = q * 2 + hi;    // 16B k-chunk this thread addresses
            uint32_t a[2][4];
#pragma unroll
            for (int mt = 0; mt < 2; mt++)
                ldm4(a[mt], sA + aoff[mt] + (uint32_t)((ch ^ ars[mt]) << 4));
            uint32_t bf[4][4];
#pragma unroll
            for (int j = 0; j < 4; j++)
                ldm4(bf[j], sB + boff[j] + (uint32_t)((ch ^ brs[j]) << 4));
            // bf[j] matrices: (n lo8, k lo4), (n hi8, k lo4), (n lo8, k hi4), (n hi8, k hi4)
#pragma unroll
            for (int mt = 0; mt < 2; mt++)
#pragma unroll
                for (int nt = 0; nt < 8; nt++)
                    mma_tf32(acc[mt][nt], a[mt], bf[nt >> 1][nt & 1], bf[nt >> 1][2 + (nt & 1)]);
        }
        __syncthreads();      // protect stage about to be overwritten next iter
    }

    // ---------------- epilogue ----------------
#pragma unroll
    for (int mt = 0; mt < 2; mt++) {
#pragma unroll
        for (int nt = 0; nt < 8; nt++) {
            const int n = tn * BN + wn * 64 + nt * 8 + tq * 2;
            const float2 bi = *(const float2*)(bias + n);
#pragma unroll
            for (int half = 0; half < 2; half++) {
                const int m = tm * BM + wm * 32 + mt * 16 + g + half * 8;
                const size_t idx = (size_t)m * NTOT + n;
                float v0 = acc[mt][nt][half * 2 + 0] + bi.x;
                float v1 = acc[mt][nt][half * 2 + 1] + bi.y;
                float2 o;
                if (EPI == 0) {
                    const float2 h = *(const float2*)(hprev + idx);
                    o.x = tf32r(sigf(v0) * h.x);
                    o.y = tf32r(sigf(v1) * h.y);
                } else if (EPI == 1) {
                    o.x = sigf(v0);
                    o.y = sigf(v1);
                } else {
                    const float2 h = *(const float2*)(hprev + idx);
                    const float2 z = *(const float2*)(zbuf + idx);
                    o.x = z.x * tanhfast(v0) + (1.f - z.x) * h.x;
                    o.y = z.y * tanhfast(v1) + (1.f - z.y) * h.y;
                }
                *(float2*)(out + idx) = o;
            }
        }
    }
}

// ---------------- host launcher ----------------
extern "C" void kernel_launch(void* const* d_in, const int* in_sizes, int n_in,
                              void* d_out, int out_size) {
    (void)in_sizes; (void)n_in; (void)out_size;
    // metadata order: x, hprev, Wh, Wz, Wr, Uh, Uz, Ur, bh, bz, br
    const float* x     = (const float*)d_in[0];
    const float* hprev = (const float*)d_in[1];
    const float* Wh    = (const float*)d_in[2];
    const float* Wz    = (const float*)d_in[3];
    const float* Wr    = (const float*)d_in[4];
    const float* Uh    = (const float*)d_in[5];
    const float* Uz    = (const float*)d_in[6];
    const float* Ur    = (const float*)d_in[7];
    const float* bh    = (const float*)d_in[8];
    const float* bz    = (const float*)d_in[9];
    const float* br    = (const float*)d_in[10];
    float* out = (float*)d_out;

    float *px, *ph, *pWr, *pWz, *pWh, *pUr, *pUz, *pUh, *prh, *pzb;
    cudaGetSymbolAddress((void**)&px,  g_x);
    cudaGetSymbolAddress((void**)&ph,  g_h);
    cudaGetSymbolAddress((void**)&pWr, g_Wr);
    cudaGetSymbolAddress((void**)&pWz, g_Wz);
    cudaGetSymbolAddress((void**)&pWh, g_Wh);
    cudaGetSymbolAddress((void**)&pUr, g_Ur);
    cudaGetSymbolAddress((void**)&pUz, g_Uz);
    cudaGetSymbolAddress((void**)&pUh, g_Uh);
    cudaGetSymbolAddress((void**)&prh, g_rh);
    cudaGetSymbolAddress((void**)&pzb, g_zb);

    cudaFuncSetAttribute(gru_gemm<0>, cudaFuncAttributeMaxDynamicSharedMemorySize, SMEM_BYTES);
    cudaFuncSetAttribute(gru_gemm<1>, cudaFuncAttributeMaxDynamicSharedMemorySize, SMEM_BYTES);
    cudaFuncSetAttribute(gru_gemm<2>, cudaFuncAttributeMaxDynamicSharedMemorySize, SMEM_BYTES);

    // tf32 pre-round all GEMM operands into scratch (one launch)
    RoundSegs S;
    S.src[0] = (const float4*)x;     S.dst[0] = (float4*)px;  S.n4[0] = MTOT * K1 / 4;
    S.src[1] = (const float4*)hprev; S.dst[1] = (float4*)ph;  S.n4[1] = MTOT * K2 / 4;
    S.src[2] = (const float4*)Wr;    S.dst[2] = (float4*)pWr; S.n4[2] = NTOT * K1 / 4;
    S.src[3] = (const float4*)Wz;    S.dst[3] = (float4*)pWz; S.n4[3] = NTOT * K1 / 4;
    S.src[4] = (const float4*)Wh;    S.dst[4] = (float4*)pWh; S.n4[4] = NTOT * K1 / 4;
    S.src[5] = (const float4*)Ur;    S.dst[5] = (float4*)pUr; S.n4[5] = NTOT * K2 / 4;
    S.src[6] = (const float4*)Uz;    S.dst[6] = (float4*)pUz; S.n4[6] = NTOT * K2 / 4;
    S.src[7] = (const float4*)Uh;    S.dst[7] = (float4*)pUh; S.n4[7] = NTOT * K2 / 4;
    round_all<<<dim3(256, 8), 256>>>(S);

    const dim3 grid(512), block(256);
    // r-gate: g_rh = tf32(sigmoid(x@Wr^T + h@Ur^T + br) * hprev)
    gru_gemm<0><<<grid, block, SMEM_BYTES>>>(px, pWr, ph, pUr, br, hprev, nullptr, prh);
    // z-gate: g_zb = sigmoid(x@Wz^T + h@Uz^T + bz)
    gru_gemm<1><<<grid, block, SMEM_BYTES>>>(px, pWz, ph, pUz, bz, nullptr, nullptr, pzb);
    // h-gate: out = z * tanh(x@Wh^T + rh@Uh^T + bh) + (1-z) * hprev
    gru_gemm<2><<<grid, block, SMEM_BYTES>>>(px, pWh, prh, pUh, bh, hprev, pzb, out);
}

// round 8
// speedup vs baseline: 1.1994x; 1.1383x over previous
#include <cuda_runtime.h>
#include <cstdint>
#include <cstddef>

// ---------------- problem constants ----------------
#define MTOT 4096
#define NTOT 2048
#define K1   1024
#define K2   2048

#define BM 128
#define BN 128
#define BK 32
#define NS 3

#define KT1  (K1 / BK)           // 32
#define KTOT ((K1 + K2) / BK)    // 96

#define STAGE_A  (BM * BK * 4)               // 16384 B
#define STAGE_SZ (2 * STAGE_A)               // 32768 B (A then B)
#define SMEM_BYTES (NS * STAGE_SZ)           // 98304 B

// ---------------- scratch (__device__ globals: allocation-free) ----------------
__device__ float g_x [MTOT * (size_t)K1];
__device__ float g_h [MTOT * (size_t)K2];
__device__ float g_Wr[NTOT * (size_t)K1];
__device__ float g_Wz[NTOT * (size_t)K1];
__device__ float g_Wh[NTOT * (size_t)K1];
__device__ float g_Ur[NTOT * (size_t)K2];
__device__ float g_Uz[NTOT * (size_t)K2];
__device__ float g_Uh[NTOT * (size_t)K2];
__device__ float g_rh[MTOT * (size_t)NTOT];
__device__ float g_zb[MTOT * (size_t)NTOT];

// ---------------- helpers ----------------
__device__ __forceinline__ uint32_t smem_u32(const void* p) {
    uint32_t a;
    asm("{ .reg .u64 t; cvta.to.shared.u64 t, %1; cvt.u32.u64 %0, t; }" : "=r"(a) : "l"(p));
    return a;
}

__device__ __forceinline__ void cp16(uint32_t dst, const void* src) {
    asm volatile("cp.async.cg.shared.global [%0], [%1], 16;" :: "r"(dst), "l"(src));
}
__device__ __forceinline__ void cp_commit() {
    asm volatile("cp.async.commit_group;" ::: "memory");
}
__device__ __forceinline__ void cp_wait1() {
    asm volatile("cp.async.wait_group 1;" ::: "memory");
}

// ldmatrix x4 (b16): four 8x8 b16 matrices == four 8row x 4col fp32 tiles.
// Fragment map (thread t -> row t/4, col t%4) matches mma.tf32 A/B layouts.
__device__ __forceinline__ void ldm4(uint32_t* r, uint32_t addr) {
    asm volatile("ldmatrix.sync.aligned.m8n8.x4.shared.b16 {%0,%1,%2,%3}, [%4];"
                 : "=r"(r[0]), "=r"(r[1]), "=r"(r[2]), "=r"(r[3]) : "r"(addr));
}

__device__ __forceinline__ void mma_tf32(float* c, const uint32_t* a, uint32_t b0, uint32_t b1) {
    asm volatile(
        "mma.sync.aligned.m16n8k8.row.col.f32.tf32.tf32.f32 "
        "{%0,%1,%2,%3}, {%4,%5,%6,%7}, {%8,%9}, {%0,%1,%2,%3};"
        : "+f"(c[0]), "+f"(c[1]), "+f"(c[2]), "+f"(c[3])
        : "r"(a[0]), "r"(a[1]), "r"(a[2]), "r"(a[3]), "r"(b0), "r"(b1));
}

__device__ __forceinline__ float tf32r(float x) {
    float r;
    asm("cvt.rna.tf32.f32 %0, %1;" : "=f"(r) : "f"(x));
    return r;
}
__device__ __forceinline__ float sigf(float v) { return 1.f / (1.f + __expf(-v)); }
__device__ __forceinline__ float tanhfast(float v) { return 2.f / (1.f + __expf(-2.f * v)) - 1.f; }

// ---------------- tf32 rounding pre-pass (one launch, 8 segments) ----------------
struct RoundSegs {
    const float4* src[8];
    float4*       dst[8];
    int           n4[8];
};

__global__ void round_all(RoundSegs S) {
    const int s = blockIdx.y;
    const float4* __restrict__ in = S.src[s];
    float4* __restrict__ out = S.dst[s];
    const int n4 = S.n4[s];
    for (int i = blockIdx.x * blockDim.x + threadIdx.x; i < n4; i += gridDim.x * blockDim.x) {
        float4 v = in[i];
        v.x = tf32r(v.x); v.y = tf32r(v.y); v.z = tf32r(v.z); v.w = tf32r(v.w);
        out[i] = v;
    }
}

// ---------------- fused dual-source GEMM ----------------
// acc[M,N] = A1@B1^T (K=1024) + A2@B2^T (K=2048), epilogue by EPI:
//  EPI 0 (r): out = tf32(sigmoid(acc+bias) * hprev)    -> g_rh
//  EPI 1 (z): out = sigmoid(acc+bias)                  -> g_zb
//  EPI 2 (h): out = z*tanh(acc+bias) + (1-z)*hprev     -> d_out
template <int EPI>
__global__ void __launch_bounds__(256, 2) gru_gemm(
    const float* __restrict__ A1, const float* __restrict__ B1,
    const float* __restrict__ A2, const float* __restrict__ B2,
    const float* __restrict__ bias, const float* __restrict__ hprev,
    const float* __restrict__ zbuf, float* __restrict__ out)
{
    extern __shared__ char smem[];
    const uint32_t sbase = smem_u32(smem);
    const int tid = threadIdx.x;
    const int wid = tid >> 5;
    const int lid = tid & 31;
    const int g   = lid >> 2;     // group id 0..7
    const int tq  = lid & 3;      // thread-in-group
    const int wm  = wid >> 1;     // 0..3 (M)
    const int wn  = wid & 1;      // 0..1 (N)
    const int tm  = blockIdx.x & 31;   // 32 M tiles
    const int tn  = blockIdx.x >> 5;   // 16 N tiles

    // -------- loader per-thread constants (hoisted out of mainloop) --------
    // row r_i = i*32 + tr, chunk c = tid&7; (r_i & 7) == (tr & 7) for all i.
    const int tr = tid >> 3;                 // 0..31
    const int c  = tid & 7;                  // 16B chunk
    const uint32_t soff = (uint32_t)tr * 128u + (uint32_t)((c ^ (tr & 7)) << 4);

    // 4 A-row + 4 B-row persistent global pointers, advanced +BK floats/tile
    const float* aptr[4];
    const float* bptr[4];
#pragma unroll
    for (int i = 0; i < 4; i++) {
        aptr[i] = A1 + (size_t)(tm * BM + i * 32 + tr) * K1 + c * 4;
        bptr[i] = B1 + (size_t)(tn * BN + i * 32 + tr) * K1 + c * 4;
    }

    // ldmatrix per-thread addressing
    const int lr = lid & 7;
    const int mi = lid >> 3;
    const int lo = mi & 1;        // +8 rows
    const int hi = mi >> 1;       // +4 k (chunk)

    uint32_t aoff[2]; int ars[2];
#pragma unroll
    for (int mt = 0; mt < 2; mt++) {
        const int r = wm * 32 + mt * 16 + lo * 8 + lr;
        aoff[mt] = (uint32_t)r * 128u;
        ars[mt] = r & 7;
    }
    uint32_t boff[4]; int brs[4];
#pragma unroll
    for (int j = 0; j < 4; j++) {
        const int r = wn * 64 + j * 16 + lo * 8 + lr;
        boff[j] = (uint32_t)r * 128u;
        brs[j] = r & 7;
    }

    float acc[2][8][4];
#pragma unroll
    for (int mt = 0; mt < 2; mt++)
#pragma unroll
        for (int nt = 0; nt < 8; nt++)
#pragma unroll
            for (int i = 0; i < 4; i++) acc[mt][nt][i] = 0.f;

    // -------- prologue: prefetch tiles 0,1 into stages 0,1 --------
#pragma unroll
    for (int p = 0; p < 2; p++) {
        const uint32_t st = sbase + p * STAGE_SZ;
#pragma unroll
        for (int i = 0; i < 4; i++) {
            cp16(st + soff + i * 4096u,           aptr[i]);
            cp16(st + STAGE_A + soff + i * 4096u, bptr[i]);
            aptr[i] += BK; bptr[i] += BK;
        }
        cp_commit();
    }

    // -------- mainloop: one sync per tile, wait_group 1 --------
#pragma unroll 1
    for (int kt0 = 0; kt0 < KTOT; kt0 += NS) {
#pragma unroll
        for (int s = 0; s < NS; s++) {
            const int kt = kt0 + s;
            cp_wait1();          // tile kt's group complete
            __syncthreads();     // visible to all; prior-iter readers done

            const int lt = kt + 2;
            if (lt < KTOT) {
                if (lt == KT1) {   // switch to second K-source
#pragma unroll
                    for (int i = 0; i < 4; i++) {
                        aptr[i] = A2 + (size_t)(tm * BM + i * 32 + tr) * K2 + c * 4;
                        bptr[i] = B2 + (size_t)(tn * BN + i * 32 + tr) * K2 + c * 4;
                    }
                }
                const uint32_t st = sbase + ((s + 2) % NS) * STAGE_SZ;
#pragma unroll
                for (int i = 0; i < 4; i++) {
                    cp16(st + soff + i * 4096u,           aptr[i]);
                    cp16(st + STAGE_A + soff + i * 4096u, bptr[i]);
                    aptr[i] += BK; bptr[i] += BK;
                }
            }
            cp_commit();         // unconditional: keeps group accounting uniform

            const uint32_t sA = sbase + s * STAGE_SZ;
            const uint32_t sB = sA + STAGE_A;
#pragma unroll
            for (int q = 0; q < 4; q++) {
                const int ch = q * 2 + hi;    // 16B k-chunk this thread addresses
                uint32_t a[2][4];
#pragma unroll
                for (int mt = 0; mt < 2; mt++)
                    ldm4(a[mt], sA + aoff[mt] + (uint32_t)((ch ^ ars[mt]) << 4));
                uint32_t bf[4][4];
#pragma unroll
                for (int j = 0; j < 4; j++)
                    ldm4(bf[j], sB + boff[j] + (uint32_t)((ch ^ brs[j]) << 4));
#pragma unroll
                for (int mt = 0; mt < 2; mt++)
#pragma unroll
                    for (int nt = 0; nt < 8; nt++)
                        mma_tf32(acc[mt][nt], a[mt], bf[nt >> 1][nt & 1], bf[nt >> 1][2 + (nt & 1)]);
            }
        }
    }

    // ---------------- epilogue ----------------
#pragma unroll
    for (int mt = 0; mt < 2; mt++) {
#pragma unroll
        for (int nt = 0; nt < 8; nt++) {
            const int n = tn * BN + wn * 64 + nt * 8 + tq * 2;
            const float2 bi = *(const float2*)(bias + n);
#pragma unroll
            for (int half = 0; half < 2; half++) {
                const int m = tm * BM + wm * 32 + mt * 16 + g + half * 8;
                const size_t idx = (size_t)m * NTOT + n;
                float v0 = acc[mt][nt][half * 2 + 0] + bi.x;
                float v1 = acc[mt][nt][half * 2 + 1] + bi.y;
                float2 o;
                if (EPI == 0) {
                    const float2 h = *(const float2*)(hprev + idx);
                    o.x = tf32r(sigf(v0) * h.x);
                    o.y = tf32r(sigf(v1) * h.y);
                } else if (EPI == 1) {
                    o.x = sigf(v0);
                    o.y = sigf(v1);
                } else {
                    const float2 h = *(const float2*)(hprev + idx);
                    const float2 z = *(const float2*)(zbuf + idx);
                    o.x = z.x * tanhfast(v0) + (1.f - z.x) * h.x;
                    o.y = z.y * tanhfast(v1) + (1.f - z.y) * h.y;
                }
                *(float2*)(out + idx) = o;
            }
        }
    }
}

// ---------------- host launcher ----------------
extern "C" void kernel_launch(void* const* d_in, const int* in_sizes, int n_in,
                              void* d_out, int out_size) {
    (void)in_sizes; (void)n_in; (void)out_size;
    // metadata order: x, hprev, Wh, Wz, Wr, Uh, Uz, Ur, bh, bz, br
    const float* x     = (const float*)d_in[0];
    const float* hprev = (const float*)d_in[1];
    const float* Wh    = (const float*)d_in[2];
    const float* Wz    = (const float*)d_in[3];
    const float* Wr    = (const float*)d_in[4];
    const float* Uh    = (const float*)d_in[5];
    const float* Uz    = (const float*)d_in[6];
    const float* Ur    = (const float*)d_in[7];
    const float* bh    = (const float*)d_in[8];
    const float* bz    = (const float*)d_in[9];
    const float* br    = (const float*)d_in[10];
    float* out = (float*)d_out;

    float *px, *ph, *pWr, *pWz, *pWh, *pUr, *pUz, *pUh, *prh, *pzb;
    cudaGetSymbolAddress((void**)&px,  g_x);
    cudaGetSymbolAddress((void**)&ph,  g_h);
    cudaGetSymbolAddress((void**)&pWr, g_Wr);
    cudaGetSymbolAddress((void**)&pWz, g_Wz);
    cudaGetSymbolAddress((void**)&pWh, g_Wh);
    cudaGetSymbolAddress((void**)&pUr, g_Ur);
    cudaGetSymbolAddress((void**)&pUz, g_Uz);
    cudaGetSymbolAddress((void**)&pUh, g_Uh);
    cudaGetSymbolAddress((void**)&prh, g_rh);
    cudaGetSymbolAddress((void**)&pzb, g_zb);

    cudaFuncSetAttribute(gru_gemm<0>, cudaFuncAttributeMaxDynamicSharedMemorySize, SMEM_BYTES);
    cudaFuncSetAttribute(gru_gemm<1>, cudaFuncAttributeMaxDynamicSharedMemorySize, SMEM_BYTES);
    cudaFuncSetAttribute(gru_gemm<2>, cudaFuncAttributeMaxDynamicSharedMemorySize, SMEM_BYTES);

    // tf32 pre-round all GEMM operands into scratch (one launch)
    RoundSegs S;
    S.src[0] = (const float4*)x;     S.dst[0] = (float4*)px;  S.n4[0] = MTOT * K1 / 4;
    S.src[1] = (const float4*)hprev; S.dst[1] = (float4*)ph;  S.n4[1] = MTOT * K2 / 4;
    S.src[2] = (const float4*)Wr;    S.dst[2] = (float4*)pWr; S.n4[2] = NTOT * K1 / 4;
    S.src[3] = (const float4*)Wz;    S.dst[3] = (float4*)pWz; S.n4[3] = NTOT * K1 / 4;
    S.src[4] = (const float4*)Wh;    S.dst[4] = (float4*)pWh; S.n4[4] = NTOT * K1 / 4;
    S.src[5] = (const float4*)Ur;    S.dst[5] = (float4*)pUr; S.n4[5] = NTOT * K2 / 4;
    S.src[6] = (const float4*)Uz;    S.dst[6] = (float4*)pUz; S.n4[6] = NTOT * K2 / 4;
    S.src[7] = (const float4*)Uh;    S.dst[7] = (float4*)pUh; S.n4[7] = NTOT * K2 / 4;
    round_all<<<dim3(256, 8), 256>>>(S);

    const dim3 grid(512), block(256);
    // r-gate: g_rh = tf32(sigmoid(x@Wr^T + h@Ur^T + br) * hprev)
    gru_gemm<0><<<grid, block, SMEM_BYTES>>>(px, pWr, ph, pUr, br, hprev, nullptr, prh);
    // z-gate: g_zb = sigmoid(x@Wz^T + h@Uz^T + bz)
    gru_gemm<1><<<grid, block, SMEM_BYTES>>>(px, pWz, ph, pUz, bz, nullptr, nullptr, pzb);
    // h-gate: out = z * tanh(x@Wh^T + rh@Uh^T + bh) + (1-z) * hprev
    gru_gemm<2><<<grid, block, SMEM_BYTES>>>(px, pWh, prh, pUh, bh, hprev, pzb, out);
}